// round 3
// baseline (speedup 1.0000x reference)
#include <cuda_runtime.h>
#include <math.h>

#define N_SEQ 2048
#define DPROJ 1024
#define C1 20000
#define C2 60000
#define V0 20000
#define V1 40000
#define V2 40000

#define NT_HEAD 158   // 157 col-tiles of 128 over 20000 cols + 1 cluster slot
#define NT_TAIL 313   // ceil(40000/128)

// ---------------- static device scratch (allocation-free, ~31 MB total) ----------------
__device__ float g_hidden[N_SEQ * DPROJ];                  // 8 MB
__device__ float g_H0[N_SEQ * DPROJ];                      // 8 MB
__device__ float g_H1[N_SEQ * 256];                        // 2 MB
__device__ float g_H2[N_SEQ * 64];                         // 0.5 MB
__device__ float2 g_part_head[(size_t)N_SEQ * NT_HEAD];    // 2.6 MB
__device__ float2 g_part_t1[(size_t)N_SEQ * NT_TAIL];      // 5.1 MB
__device__ float2 g_part_t2[(size_t)N_SEQ * NT_TAIL];      // 5.1 MB
__device__ float g_head_lse[N_SEQ];
__device__ float g_t1_lse[N_SEQ];
__device__ float g_t2_lse[N_SEQ];
__device__ float g_lab_head[N_SEQ];
__device__ float g_lab_t1[N_SEQ];
__device__ float g_lab_t2[N_SEQ];
__device__ float g_clus[N_SEQ][2];
__device__ int g_xl[3][N_SEQ];     // token index per x-cluster (scatter rows for hidden)
__device__ int g_xar[3][N_SEQ];    // embedding-table row per x-cluster (gather rows)
__device__ int g_ll[2][N_SEQ];     // token index per label tail-cluster (compact lists)
__device__ int g_pos[2][N_SEQ];    // token -> compact position in its tail list
__device__ int g_labc_head[N_SEQ]; // wanted head col per row (or -1)
__device__ int g_labc_t1[N_SEQ];   // wanted tail1 col per compact row
__device__ int g_labc_t2[N_SEQ];   // wanted tail2 col per compact row
__device__ int g_cnt[8];           // [0..2]=x-cluster counts, [3..4]=label tail counts

// ---------------- list building (deterministic prefix scan, 1 block) ----------------
__global__ void build_lists(const int* __restrict__ x, const int* __restrict__ labels) {
    __shared__ int base[5][257];
    const int tid = threadIdx.x;      // 256 threads, 8 tokens each
    int lc[5] = {0, 0, 0, 0, 0};
    for (int t = tid * 8; t < tid * 8 + 8; t++) {
        int xv = x[t];
        int c = (xv < C1) ? 0 : ((xv < C2) ? 1 : 2);
        lc[c]++;
        int lv = labels[t];
        if (lv >= C1) lc[3 + (lv >= C2 ? 1 : 0)]++;
    }
    for (int c = 0; c < 5; c++) base[c][tid + 1] = lc[c];
    __syncthreads();
    if (tid < 5) {
        base[tid][0] = 0;
        for (int i = 0; i < 256; i++) base[tid][i + 1] += base[tid][i];
        g_cnt[tid] = base[tid][256];
    }
    __syncthreads();
    int off[5];
    for (int c = 0; c < 5; c++) off[c] = base[c][tid];
    for (int t = tid * 8; t < tid * 8 + 8; t++) {
        int xv = x[t];
        int c = (xv < C1) ? 0 : ((xv < C2) ? 1 : 2);
        int lo = (c == 0) ? 0 : ((c == 1) ? C1 : C2);
        int p = off[c]++;
        g_xl[c][p] = t;
        g_xar[c][p] = xv - lo;
        int lv = labels[t];
        g_labc_head[t] = (lv < C1) ? lv : -1;
        if (lv >= C1) {
            int tc = (lv >= C2) ? 1 : 0;
            int q = off[3 + tc]++;
            g_ll[tc][q] = t;
            g_pos[tc][t] = q;
            if (tc == 0) g_labc_t1[q] = lv - C1;
            else         g_labc_t2[q] = lv - C2;
        }
    }
}

// ---------------- NT GEMM body (inlined into wrappers) ----------------
// A: [*, K] row-major, B: [N, K] row-major. BM=BN=128, BK=8, 256 threads, 8x8/thread.
// FUSED=false: C[cr(m), n] = alpha*acc + bias[n].
// FUSED=true : no C write; per-(row, col-tile) online (max, sumexp) partial in
//              part[m*ntiles + bx] plus label-logit capture via labc/labout.
template <bool FUSED>
__device__ __forceinline__ void gemm_nt_body(
    const float* __restrict__ A, const float* __restrict__ B, float* __restrict__ C,
    int M, int N, int K, long ldC,
    const int* __restrict__ arows, const int* __restrict__ crows,
    const float* __restrict__ bias, float alpha, const int* __restrict__ Mcnt,
    float2* __restrict__ part, int ntiles,
    const int* __restrict__ labc, float* __restrict__ labout)
{
    if (Mcnt) M = *Mcnt;
    const int bm = blockIdx.y * 128, bn = blockIdx.x * 128;
    if (bm >= M) return;
    __shared__ __align__(16) float As[8][132];
    __shared__ __align__(16) float Bs[8][132];
    const int tid = threadIdx.x;
    const int tx = tid & 15, ty = tid >> 4;
    const int lr = tid >> 1;         // 0..127 : tile row being loaded
    const int lk = (tid & 1) * 4;    // k sub-offset 0 or 4

    const float* aptr = nullptr;
    { int m = bm + lr; if (m < M) { int g = arows ? arows[m] : m; aptr = A + (long)g * K + lk; } }
    const float* bptr = nullptr;
    { int n = bn + lr; if (n < N) bptr = B + (long)n * K + lk; }

    float4 av = aptr ? *(const float4*)aptr : make_float4(0, 0, 0, 0);
    float4 bv = bptr ? *(const float4*)bptr : make_float4(0, 0, 0, 0);

    float acc[8][8] = {};
    for (int k0 = 0; k0 < K; k0 += 8) {
        __syncthreads();
        As[lk + 0][lr] = av.x; As[lk + 1][lr] = av.y; As[lk + 2][lr] = av.z; As[lk + 3][lr] = av.w;
        Bs[lk + 0][lr] = bv.x; Bs[lk + 1][lr] = bv.y; Bs[lk + 2][lr] = bv.z; Bs[lk + 3][lr] = bv.w;
        __syncthreads();
        if (k0 + 8 < K) {
            av = aptr ? *(const float4*)(aptr + k0 + 8) : make_float4(0, 0, 0, 0);
            bv = bptr ? *(const float4*)(bptr + k0 + 8) : make_float4(0, 0, 0, 0);
        }
#pragma unroll
        for (int k = 0; k < 8; k++) {
            float4 a0 = *(const float4*)&As[k][ty * 8];
            float4 a1 = *(const float4*)&As[k][ty * 8 + 4];
            float4 b0 = *(const float4*)&Bs[k][tx * 8];
            float4 b1 = *(const float4*)&Bs[k][tx * 8 + 4];
            float ar[8] = {a0.x, a0.y, a0.z, a0.w, a1.x, a1.y, a1.z, a1.w};
            float br[8] = {b0.x, b0.y, b0.z, b0.w, b1.x, b1.y, b1.z, b1.w};
#pragma unroll
            for (int i = 0; i < 8; i++)
#pragma unroll
                for (int j = 0; j < 8; j++) acc[i][j] = fmaf(ar[i], br[j], acc[i][j]);
        }
    }

    if (FUSED) {
#pragma unroll
        for (int i = 0; i < 8; i++) {
            int m = bm + ty * 8 + i;
            if (m >= M) break;
            const int lc = labc[m];
            float vmax = -1e30f;
            float vals[8];
#pragma unroll
            for (int j = 0; j < 8; j++) {
                int n = bn + tx * 8 + j;
                float v = (n < N) ? acc[i][j] + bias[n] : -1e30f;
                vals[j] = v;
                if (v > vmax) vmax = v;
                if (n == lc) labout[m] = v;
            }
#pragma unroll
            for (int o = 8; o > 0; o >>= 1)
                vmax = fmaxf(vmax, __shfl_xor_sync(0xffffffffu, vmax, o));
            float s = 0.f;
#pragma unroll
            for (int j = 0; j < 8; j++) s += __expf(vals[j] - vmax);
#pragma unroll
            for (int o = 8; o > 0; o >>= 1)
                s += __shfl_xor_sync(0xffffffffu, s, o);
            if (tx == 0)
                part[(long)m * ntiles + blockIdx.x] = make_float2(vmax, s);
        }
    } else {
#pragma unroll
        for (int i = 0; i < 8; i++) {
            int m = bm + ty * 8 + i;
            if (m >= M) break;
            long cr = crows ? (long)crows[m] : (long)m;
            float* crow = C + cr * ldC;
#pragma unroll
            for (int j = 0; j < 8; j++) {
                int n = bn + tx * 8 + j;
                if (n < N) crow[n] = acc[i][j] * alpha;
            }
        }
    }
}

// ---------------- NN GEMM body: C[m, n] = A[ar(m),:] . B[:, n] (B: [K,N] row-major) ----------------
__device__ __forceinline__ void gemm_nn_body(
    const float* __restrict__ A, const float* __restrict__ B, float* __restrict__ C,
    int M, int N, int K, const int* __restrict__ arows, const int* __restrict__ Mcnt)
{
    if (Mcnt) M = *Mcnt;
    const int bm = blockIdx.y * 128, bn = blockIdx.x * 128;
    if (bm >= M) return;
    __shared__ __align__(16) float As[8][132];
    __shared__ __align__(16) float Bs[8][132];
    const int tid = threadIdx.x;
    const int tx = tid & 15, ty = tid >> 4;
    const int lr = tid >> 1;
    const int lk = (tid & 1) * 4;
    const int bk = tid >> 5;             // 0..7
    const int bnn = (tid & 31) * 4;      // 0..124

    const float* aptr = nullptr;
    { int m = bm + lr; if (m < M) { int g = arows ? arows[m] : m; aptr = A + (long)g * K + lk; } }
    const bool bok = (bn + bnn) < N;
    const float* bbase = B + (long)bk * N + bn + bnn;

    float4 av = aptr ? *(const float4*)aptr : make_float4(0, 0, 0, 0);
    float4 bv = bok ? *(const float4*)bbase : make_float4(0, 0, 0, 0);

    float acc[8][8] = {};
    for (int k0 = 0; k0 < K; k0 += 8) {
        __syncthreads();
        As[lk + 0][lr] = av.x; As[lk + 1][lr] = av.y; As[lk + 2][lr] = av.z; As[lk + 3][lr] = av.w;
        *(float4*)&Bs[bk][bnn] = bv;
        __syncthreads();
        if (k0 + 8 < K) {
            av = aptr ? *(const float4*)(aptr + k0 + 8) : make_float4(0, 0, 0, 0);
            bv = bok ? *(const float4*)(bbase + (long)(k0 + 8) * N) : make_float4(0, 0, 0, 0);
        }
#pragma unroll
        for (int k = 0; k < 8; k++) {
            float4 a0 = *(const float4*)&As[k][ty * 8];
            float4 a1 = *(const float4*)&As[k][ty * 8 + 4];
            float4 b0 = *(const float4*)&Bs[k][tx * 8];
            float4 b1 = *(const float4*)&Bs[k][tx * 8 + 4];
            float ar[8] = {a0.x, a0.y, a0.z, a0.w, a1.x, a1.y, a1.z, a1.w};
            float br[8] = {b0.x, b0.y, b0.z, b0.w, b1.x, b1.y, b1.z, b1.w};
#pragma unroll
            for (int i = 0; i < 8; i++)
#pragma unroll
                for (int j = 0; j < 8; j++) acc[i][j] = fmaf(ar[i], br[j], acc[i][j]);
        }
    }
#pragma unroll
    for (int i = 0; i < 8; i++) {
        int m = bm + ty * 8 + i;
        if (m >= M) break;
        float* crow = C + (long)m * N;
#pragma unroll
        for (int j = 0; j < 8; j++) {
            int n = bn + tx * 8 + j;
            if (n < N) crow[n] = acc[i][j];
        }
    }
}

// ---------------- wrapper kernels (scratch globals referenced in device code) ----------------
__global__ void __launch_bounds__(256) k_emb0(const float* __restrict__ W, const float* __restrict__ P) {
    gemm_nt_body<false>(W, P, g_hidden, N_SEQ, DPROJ, 1024, DPROJ,
                        g_xar[0], g_xl[0], nullptr, 32.f, &g_cnt[0], nullptr, 0, nullptr, nullptr);
}
__global__ void __launch_bounds__(256) k_emb1(const float* __restrict__ W, const float* __restrict__ P) {
    gemm_nt_body<false>(W, P, g_hidden, N_SEQ, DPROJ, 256, DPROJ,
                        g_xar[1], g_xl[1], nullptr, 32.f, &g_cnt[1], nullptr, 0, nullptr, nullptr);
}
__global__ void __launch_bounds__(256) k_emb2(const float* __restrict__ W, const float* __restrict__ P) {
    gemm_nt_body<false>(W, P, g_hidden, N_SEQ, DPROJ, 64, DPROJ,
                        g_xar[2], g_xl[2], nullptr, 32.f, &g_cnt[2], nullptr, 0, nullptr, nullptr);
}
__global__ void __launch_bounds__(256) k_proj0(const float* __restrict__ P) {
    gemm_nn_body(g_hidden, P, g_H0, N_SEQ, DPROJ, 1024, nullptr, nullptr);
}
__global__ void __launch_bounds__(256) k_proj1(const float* __restrict__ P) {
    gemm_nn_body(g_hidden, P, g_H1, N_SEQ, 256, 1024, g_ll[0], &g_cnt[3]);
}
__global__ void __launch_bounds__(256) k_proj2(const float* __restrict__ P) {
    gemm_nn_body(g_hidden, P, g_H2, N_SEQ, 64, 1024, g_ll[1], &g_cnt[4]);
}
__global__ void __launch_bounds__(256) k_head(const float* __restrict__ W, const float* __restrict__ bias) {
    gemm_nt_body<true>(g_H0, W, nullptr, N_SEQ, V0, 1024, 0,
                       nullptr, nullptr, bias, 1.f, nullptr,
                       g_part_head, NT_HEAD, g_labc_head, g_lab_head);
}
__global__ void __launch_bounds__(256) k_tail1(const float* __restrict__ W, const float* __restrict__ bias) {
    gemm_nt_body<true>(g_H1, W, nullptr, N_SEQ, V1, 256, 0,
                       nullptr, nullptr, bias, 1.f, &g_cnt[3],
                       g_part_t1, NT_TAIL, g_labc_t1, g_lab_t1);
}
__global__ void __launch_bounds__(256) k_tail2(const float* __restrict__ W, const float* __restrict__ bias) {
    gemm_nt_body<true>(g_H2, W, nullptr, N_SEQ, V2, 64, 0,
                       nullptr, nullptr, bias, 1.f, &g_cnt[4],
                       g_part_t2, NT_TAIL, g_labc_t2, g_lab_t2);
}

// ---------------- cluster-token logits (head cols 20000, 20001) + their LSE partial ----------------
__global__ void __launch_bounds__(128) cluster_cols(const float* __restrict__ cw,
                                                    const float* __restrict__ cb) {
    const int r = blockIdx.x;
    const float* h = g_H0 + (size_t)r * DPROJ;
    float s0 = 0.f, s1 = 0.f;
    for (int k = threadIdx.x; k < DPROJ; k += 128) {
        float hv = h[k];
        s0 = fmaf(hv, cw[k], s0);
        s1 = fmaf(hv, cw[DPROJ + k], s1);
    }
#pragma unroll
    for (int o = 16; o > 0; o >>= 1) {
        s0 += __shfl_down_sync(0xffffffffu, s0, o);
        s1 += __shfl_down_sync(0xffffffffu, s1, o);
    }
    __shared__ float red[2][4];
    const int wid = threadIdx.x >> 5, lane = threadIdx.x & 31;
    if (lane == 0) { red[0][wid] = s0; red[1][wid] = s1; }
    __syncthreads();
    if (threadIdx.x == 0) {
        float c0 = red[0][0] + red[0][1] + red[0][2] + red[0][3] + cb[0];
        float c1 = red[1][0] + red[1][1] + red[1][2] + red[1][3] + cb[1];
        g_clus[r][0] = c0;
        g_clus[r][1] = c1;
        float pm = fmaxf(c0, c1);
        g_part_head[(size_t)r * NT_HEAD + (NT_HEAD - 1)] =
            make_float2(pm, __expf(c0 - pm) + __expf(c1 - pm));
    }
}

// ---------------- combine per-tile partials into the row LSE (1 warp / row) ----------------
template <int NT, int WHICH>   // WHICH: 0=head, 1=tail1, 2=tail2
__global__ void __launch_bounds__(256) reduce_lse() {
    const int r = blockIdx.x * 8 + (threadIdx.x >> 5);
    const int lane = threadIdx.x & 31;
    if (WHICH == 1 && r >= g_cnt[3]) return;
    if (WHICH == 2 && r >= g_cnt[4]) return;
    const float2* part = (WHICH == 0) ? g_part_head : (WHICH == 1) ? g_part_t1 : g_part_t2;
    float m = -1e30f, s = 0.f;
    for (int t = lane; t < NT; t += 32) {
        float2 p = part[(long)r * NT + t];
        if (p.x > m) { s = s * __expf(m - p.x) + p.y; m = p.x; }
        else s += p.y * __expf(p.x - m);
    }
#pragma unroll
    for (int o = 16; o > 0; o >>= 1) {
        float m2 = __shfl_xor_sync(0xffffffffu, m, o);
        float s2 = __shfl_xor_sync(0xffffffffu, s, o);
        float mm = fmaxf(m, m2);
        s = s * __expf(m - mm) + s2 * __expf(m2 - mm);
        m = mm;
    }
    if (lane == 0) {
        float v = m + logf(s);
        if (WHICH == 0) g_head_lse[r] = v;
        else if (WHICH == 1) g_t1_lse[r] = v;
        else g_t2_lse[r] = v;
    }
}

// ---------------- finalize: assemble per-row logprob, emit NLL ----------------
__global__ void __launch_bounds__(256) finalize_k(const int* __restrict__ labels,
                                                  float* __restrict__ out) {
    const int r = blockIdx.x * 256 + threadIdx.x;
    if (r >= N_SEQ) return;
    const int l = labels[r];
    const float lse = g_head_lse[r];
    float lp;
    if (l < C1) {
        lp = g_lab_head[r] - lse;
    } else if (l < C2) {
        int p = g_pos[0][r];
        lp = (g_clus[r][1] - lse) + (g_lab_t1[p] - g_t1_lse[p]);
    } else {
        int p = g_pos[1][r];
        lp = (g_clus[r][0] - lse) + (g_lab_t2[p] - g_t2_lse[p]);
    }
    out[r] = -lp;
}

// ---------------- launch: kernel launches ONLY, no other API calls ----------------
extern "C" void kernel_launch(void* const* d_in, const int* in_sizes, int n_in,
                              void* d_out, int out_size) {
    const int* x        = (const int*)d_in[0];
    const int* labels   = (const int*)d_in[1];
    const float* emb_w0 = (const float*)d_in[2];
    const float* emb_w1 = (const float*)d_in[3];
    const float* emb_w2 = (const float*)d_in[4];
    const float* emb_p0 = (const float*)d_in[5];
    const float* emb_p1 = (const float*)d_in[6];
    const float* emb_p2 = (const float*)d_in[7];
    const float* out_w0 = (const float*)d_in[8];
    const float* out_b0 = (const float*)d_in[9];
    const float* out_w1 = (const float*)d_in[10];
    const float* out_b1 = (const float*)d_in[11];
    const float* out_w2 = (const float*)d_in[12];
    const float* out_b2 = (const float*)d_in[13];
    const float* out_p0 = (const float*)d_in[14];
    const float* out_p1 = (const float*)d_in[15];
    const float* out_p2 = (const float*)d_in[16];
    const float* clus_w = (const float*)d_in[17];
    const float* clus_b = (const float*)d_in[18];

    // 1) cluster lists
    build_lists<<<1, 256>>>(x, labels);

    // 2) adaptive embedding: hidden[tok,:] = 32 * emb_w_c[x-lo,:] @ emb_proj_c^T
    dim3 eg(DPROJ / 128, N_SEQ / 128);   // (8,16), early-exit beyond count
    k_emb0<<<eg, 256>>>(emb_w0, emb_p0);
    k_emb1<<<eg, 256>>>(emb_w1, emb_p1);
    k_emb2<<<eg, 256>>>(emb_w2, emb_p2);

    // 3) H0 = hidden @ out_proj0 (all rows)
    k_proj0<<<dim3(8, 16), 256>>>(out_p0);

    // 4) head logits: fused LSE partials + label capture; plus cluster-token columns
    k_head<<<dim3((V0 + 127) / 128, 16), 256>>>(out_w0, out_b0);
    cluster_cols<<<N_SEQ, 128>>>(clus_w, clus_b);

    // 5) tail hidden projections (compacted rows only)
    k_proj1<<<dim3(2, 16), 256>>>(out_p1);
    k_proj2<<<dim3(1, 16), 256>>>(out_p2);

    // 6) tail logits: fused LSE partials + label capture (compacted rows only)
    k_tail1<<<dim3((V1 + 127) / 128, 16), 256>>>(out_w1, out_b1);
    k_tail2<<<dim3((V2 + 127) / 128, 16), 256>>>(out_w2, out_b2);

    // 7) combine partials -> per-row LSE
    reduce_lse<NT_HEAD, 0><<<N_SEQ / 8, 256>>>();
    reduce_lse<NT_TAIL, 1><<<N_SEQ / 8, 256>>>();
    reduce_lse<NT_TAIL, 2><<<N_SEQ / 8, 256>>>();

    // 8) final NLL
    finalize_k<<<N_SEQ / 256, 256>>>(labels, (float*)d_out);
}

// round 5
// speedup vs baseline: 2.6200x; 2.6200x over previous
#include <cuda_runtime.h>
#include <cuda_bf16.h>
#include <math.h>
#include <stdint.h>

#define N_SEQ 2048
#define DPROJ 1024
#define C1 20000
#define C2 60000
#define V0 20000
#define V1 40000
#define V2 40000

#define NT0 157        // ceil(20000/128) head col tiles
#define NT_HEAD 158    // +1 cluster slot
#define NT_TAIL 313    // ceil(40000/128)

// ---------------- static device scratch (allocation-free) ----------------
__device__ float g_hidden[N_SEQ * DPROJ];
__device__ __nv_bfloat16 g_hidden_b[N_SEQ * DPROJ];
__device__ float g_H0[N_SEQ * DPROJ];
__device__ __nv_bfloat16 g_H0b[N_SEQ * DPROJ];
__device__ __nv_bfloat16 g_H1b[N_SEQ * 256];
__device__ __nv_bfloat16 g_H2b[N_SEQ * 64];
__device__ __nv_bfloat16 g_w0b[(size_t)V0 * 1024];
__device__ __nv_bfloat16 g_w1b[(size_t)V1 * 256];
__device__ __nv_bfloat16 g_w2b[(size_t)V2 * 64];
__device__ __nv_bfloat16 g_p0t[(size_t)DPROJ * DPROJ];   // out_proj0 transposed: [n][k]
__device__ float2 g_part_head[(size_t)N_SEQ * NT_HEAD];
__device__ float2 g_part_t1[(size_t)N_SEQ * NT_TAIL];
__device__ float2 g_part_t2[(size_t)N_SEQ * NT_TAIL];
__device__ float g_head_lse[N_SEQ];
__device__ float g_t1_lse[N_SEQ];
__device__ float g_t2_lse[N_SEQ];
__device__ float g_lab_head[N_SEQ];
__device__ float g_lab_t1[N_SEQ];
__device__ float g_lab_t2[N_SEQ];
__device__ float g_clus[N_SEQ][2];
__device__ int g_xl[3][N_SEQ];
__device__ int g_xar[3][N_SEQ];
__device__ int g_ll[2][N_SEQ];
__device__ int g_pos[2][N_SEQ];
__device__ int g_labc_head[N_SEQ];
__device__ int g_labc_t1[N_SEQ];
__device__ int g_labc_t2[N_SEQ];
__device__ int g_cnt[8];

// ---------------- helpers ----------------
static __device__ __forceinline__ uint32_t smem_u32(const void* p) {
    uint32_t a;
    asm("{ .reg .u64 t; cvta.to.shared.u64 t, %1; cvt.u32.u64 %0, t; }" : "=r"(a) : "l"(p));
    return a;
}

// FMA-pipe exp (no MUFU): exp(x)=2^(x*log2e), deg-5 poly
static __device__ __forceinline__ float fexp(float x) {
    float y = fmaxf(x * 1.44269504f, -120.f);
    int e = __float2int_rn(y);
    float f = y - __int2float_rn(e);
    float p = 1.3333558e-3f;
    p = fmaf(p, f, 9.6181291e-3f);
    p = fmaf(p, f, 5.5504109e-2f);
    p = fmaf(p, f, 2.4022650e-1f);
    p = fmaf(p, f, 6.9314718e-1f);
    p = fmaf(p, f, 1.0f);
    return p * __int_as_float((e + 127) << 23);
}

static __device__ __forceinline__ void ldm_x4(uint32_t* r, uint32_t addr) {
    asm volatile("ldmatrix.sync.aligned.m8n8.x4.shared.b16 {%0,%1,%2,%3}, [%4];"
                 : "=r"(r[0]), "=r"(r[1]), "=r"(r[2]), "=r"(r[3]) : "r"(addr));
}
static __device__ __forceinline__ void ldm_x2(uint32_t* r, uint32_t addr) {
    asm volatile("ldmatrix.sync.aligned.m8n8.x2.shared.b16 {%0,%1}, [%2];"
                 : "=r"(r[0]), "=r"(r[1]) : "r"(addr));
}
static __device__ __forceinline__ void mma_bf16(float* c, const uint32_t* a, const uint32_t* b) {
    asm volatile(
        "mma.sync.aligned.m16n8k16.row.col.f32.bf16.bf16.f32 "
        "{%0,%1,%2,%3}, {%4,%5,%6,%7}, {%8,%9}, {%0,%1,%2,%3};"
        : "+f"(c[0]), "+f"(c[1]), "+f"(c[2]), "+f"(c[3])
        : "r"(a[0]), "r"(a[1]), "r"(a[2]), "r"(a[3]), "r"(b[0]), "r"(b[1]));
}

// ---------------- list building (1 block, deterministic prefix scan) ----------------
__global__ void build_lists(const int* __restrict__ x, const int* __restrict__ labels) {
    __shared__ int base[5][257];
    const int tid = threadIdx.x;
    int lc[5] = {0, 0, 0, 0, 0};
    for (int t = tid * 8; t < tid * 8 + 8; t++) {
        int xv = x[t];
        int c = (xv < C1) ? 0 : ((xv < C2) ? 1 : 2);
        lc[c]++;
        int lv = labels[t];
        if (lv >= C1) lc[3 + (lv >= C2 ? 1 : 0)]++;
    }
    for (int c = 0; c < 5; c++) base[c][tid + 1] = lc[c];
    __syncthreads();
    if (tid < 5) {
        base[tid][0] = 0;
        for (int i = 0; i < 256; i++) base[tid][i + 1] += base[tid][i];
        g_cnt[tid] = base[tid][256];
    }
    __syncthreads();
    int off[5];
    for (int c = 0; c < 5; c++) off[c] = base[c][tid];
    for (int t = tid * 8; t < tid * 8 + 8; t++) {
        int xv = x[t];
        int c = (xv < C1) ? 0 : ((xv < C2) ? 1 : 2);
        int lo = (c == 0) ? 0 : ((c == 1) ? C1 : C2);
        int p = off[c]++;
        g_xl[c][p] = t;
        g_xar[c][p] = xv - lo;
        int lv = labels[t];
        g_labc_head[t] = (lv < C1) ? lv : -1;
        if (lv >= C1) {
            int tc = (lv >= C2) ? 1 : 0;
            int q = off[3 + tc]++;
            g_ll[tc][q] = t;
            g_pos[tc][t] = q;
            if (tc == 0) g_labc_t1[q] = lv - C1;
            else         g_labc_t2[q] = lv - C2;
        }
    }
}

// ---------------- weight conversion fp32 -> bf16 ----------------
template <int W>
__global__ void __launch_bounds__(256) cvt_k(const float* __restrict__ src) {
    __nv_bfloat16* dst = (W == 0) ? g_w0b : (W == 1) ? g_w1b : g_w2b;
    const int n = (W == 0) ? V0 * 1024 : (W == 1) ? V1 * 256 : V2 * 64;
    int i = (blockIdx.x * 256 + threadIdx.x) * 4;
    const int stride = gridDim.x * 256 * 4;
    for (; i < n; i += stride) {
        float4 v = *(const float4*)(src + i);
        *(__nv_bfloat162*)(dst + i)     = __floats2bfloat162_rn(v.x, v.y);
        *(__nv_bfloat162*)(dst + i + 2) = __floats2bfloat162_rn(v.z, v.w);
    }
}

// out_proj0 [K=1024, N=1024] fp32 -> g_p0t [N, K] bf16
__global__ void transpose_p0(const float* __restrict__ src) {
    __shared__ float t[32][33];
    const int k0 = blockIdx.y * 32, n0 = blockIdx.x * 32;
    const int tx = threadIdx.x, ty = threadIdx.y;   // 32 x 8
    for (int r = ty; r < 32; r += 8)
        t[r][tx] = src[(size_t)(k0 + r) * DPROJ + n0 + tx];
    __syncthreads();
    for (int r = ty; r < 32; r += 8)
        g_p0t[(size_t)(n0 + r) * DPROJ + k0 + tx] = __float2bfloat16(t[tx][r]);
}

// ---------------- SIMT fp32 NT GEMM (embeddings; dual fp32+bf16 scatter store) ----------------
__device__ __forceinline__ void gemm_nt_body(
    const float* __restrict__ A, const float* __restrict__ B,
    float* __restrict__ Cf, __nv_bfloat16* __restrict__ Cb,
    int M, int N, int K, long ldC,
    const int* __restrict__ arows, const int* __restrict__ crows,
    float alpha, const int* __restrict__ Mcnt)
{
    if (Mcnt) M = *Mcnt;
    const int bm = blockIdx.y * 128, bn = blockIdx.x * 128;
    if (bm >= M) return;
    __shared__ __align__(16) float As[8][132];
    __shared__ __align__(16) float Bs[8][132];
    const int tid = threadIdx.x;
    const int tx = tid & 15, ty = tid >> 4;
    const int lr = tid >> 1;
    const int lk = (tid & 1) * 4;

    const float* aptr = nullptr;
    { int m = bm + lr; if (m < M) { int g = arows ? arows[m] : m; aptr = A + (long)g * K + lk; } }
    const float* bptr = nullptr;
    { int n = bn + lr; if (n < N) bptr = B + (long)n * K + lk; }

    float4 av = aptr ? *(const float4*)aptr : make_float4(0, 0, 0, 0);
    float4 bv = bptr ? *(const float4*)bptr : make_float4(0, 0, 0, 0);

    float acc[8][8] = {};
    for (int k0 = 0; k0 < K; k0 += 8) {
        __syncthreads();
        As[lk + 0][lr] = av.x; As[lk + 1][lr] = av.y; As[lk + 2][lr] = av.z; As[lk + 3][lr] = av.w;
        Bs[lk + 0][lr] = bv.x; Bs[lk + 1][lr] = bv.y; Bs[lk + 2][lr] = bv.z; Bs[lk + 3][lr] = bv.w;
        __syncthreads();
        if (k0 + 8 < K) {
            av = aptr ? *(const float4*)(aptr + k0 + 8) : make_float4(0, 0, 0, 0);
            bv = bptr ? *(const float4*)(bptr + k0 + 8) : make_float4(0, 0, 0, 0);
        }
#pragma unroll
        for (int k = 0; k < 8; k++) {
            float4 a0 = *(const float4*)&As[k][ty * 8];
            float4 a1 = *(const float4*)&As[k][ty * 8 + 4];
            float4 b0 = *(const float4*)&Bs[k][tx * 8];
            float4 b1 = *(const float4*)&Bs[k][tx * 8 + 4];
            float ar[8] = {a0.x, a0.y, a0.z, a0.w, a1.x, a1.y, a1.z, a1.w};
            float br[8] = {b0.x, b0.y, b0.z, b0.w, b1.x, b1.y, b1.z, b1.w};
#pragma unroll
            for (int i = 0; i < 8; i++)
#pragma unroll
                for (int j = 0; j < 8; j++) acc[i][j] = fmaf(ar[i], br[j], acc[i][j]);
        }
    }
#pragma unroll
    for (int i = 0; i < 8; i++) {
        int m = bm + ty * 8 + i;
        if (m >= M) break;
        long cr = crows ? (long)crows[m] : (long)m;
#pragma unroll
        for (int j = 0; j < 8; j++) {
            int n = bn + tx * 8 + j;
            if (n < N) {
                float v = acc[i][j] * alpha;
                Cf[cr * ldC + n] = v;
                Cb[cr * ldC + n] = __float2bfloat16(v);
            }
        }
    }
}

// ---------------- SIMT fp32 NN GEMM (proj1/proj2; bf16 store) ----------------
__device__ __forceinline__ void gemm_nn_body(
    const float* __restrict__ A, const float* __restrict__ B,
    __nv_bfloat16* __restrict__ Cb,
    int M, int N, int K, const int* __restrict__ arows, const int* __restrict__ Mcnt)
{
    if (Mcnt) M = *Mcnt;
    const int bm = blockIdx.y * 128, bn = blockIdx.x * 128;
    if (bm >= M) return;
    __shared__ __align__(16) float As[8][132];
    __shared__ __align__(16) float Bs[8][132];
    const int tid = threadIdx.x;
    const int tx = tid & 15, ty = tid >> 4;
    const int lr = tid >> 1;
    const int lk = (tid & 1) * 4;
    const int bk = tid >> 5;
    const int bnn = (tid & 31) * 4;

    const float* aptr = nullptr;
    { int m = bm + lr; if (m < M) { int g = arows ? arows[m] : m; aptr = A + (long)g * K + lk; } }
    const bool bok = (bn + bnn) < N;
    const float* bbase = B + (long)bk * N + bn + bnn;

    float4 av = aptr ? *(const float4*)aptr : make_float4(0, 0, 0, 0);
    float4 bv = bok ? *(const float4*)bbase : make_float4(0, 0, 0, 0);

    float acc[8][8] = {};
    for (int k0 = 0; k0 < K; k0 += 8) {
        __syncthreads();
        As[lk + 0][lr] = av.x; As[lk + 1][lr] = av.y; As[lk + 2][lr] = av.z; As[lk + 3][lr] = av.w;
        *(float4*)&Bs[bk][bnn] = bv;
        __syncthreads();
        if (k0 + 8 < K) {
            av = aptr ? *(const float4*)(aptr + k0 + 8) : make_float4(0, 0, 0, 0);
            bv = bok ? *(const float4*)(bbase + (long)(k0 + 8) * N) : make_float4(0, 0, 0, 0);
        }
#pragma unroll
        for (int k = 0; k < 8; k++) {
            float4 a0 = *(const float4*)&As[k][ty * 8];
            float4 a1 = *(const float4*)&As[k][ty * 8 + 4];
            float4 b0 = *(const float4*)&Bs[k][tx * 8];
            float4 b1 = *(const float4*)&Bs[k][tx * 8 + 4];
            float ar[8] = {a0.x, a0.y, a0.z, a0.w, a1.x, a1.y, a1.z, a1.w};
            float br[8] = {b0.x, b0.y, b0.z, b0.w, b1.x, b1.y, b1.z, b1.w};
#pragma unroll
            for (int i = 0; i < 8; i++)
#pragma unroll
                for (int j = 0; j < 8; j++) acc[i][j] = fmaf(ar[i], br[j], acc[i][j]);
        }
    }
#pragma unroll
    for (int i = 0; i < 8; i++) {
        int m = bm + ty * 8 + i;
        if (m >= M) break;
#pragma unroll
        for (int j = 0; j < 8; j++) {
            int n = bn + tx * 8 + j;
            if (n < N) Cb[(long)m * N + n] = __float2bfloat16(acc[i][j]);
        }
    }
}

__global__ void __launch_bounds__(256) k_emb0(const float* __restrict__ W, const float* __restrict__ P) {
    gemm_nt_body(W, P, g_hidden, g_hidden_b, N_SEQ, DPROJ, 1024, DPROJ, g_xar[0], g_xl[0], 32.f, &g_cnt[0]);
}
__global__ void __launch_bounds__(256) k_emb1(const float* __restrict__ W, const float* __restrict__ P) {
    gemm_nt_body(W, P, g_hidden, g_hidden_b, N_SEQ, DPROJ, 256, DPROJ, g_xar[1], g_xl[1], 32.f, &g_cnt[1]);
}
__global__ void __launch_bounds__(256) k_emb2(const float* __restrict__ W, const float* __restrict__ P) {
    gemm_nt_body(W, P, g_hidden, g_hidden_b, N_SEQ, DPROJ, 64, DPROJ, g_xar[2], g_xl[2], 32.f, &g_cnt[2]);
}
__global__ void __launch_bounds__(256) k_proj1(const float* __restrict__ P) {
    gemm_nn_body(g_hidden, P, g_H1b, N_SEQ, 256, 1024, g_ll[0], &g_cnt[3]);
}
__global__ void __launch_bounds__(256) k_proj2(const float* __restrict__ P) {
    gemm_nn_body(g_hidden, P, g_H2b, N_SEQ, 64, 1024, g_ll[1], &g_cnt[4]);
}

// ---------------- mma.sync bf16 NT GEMM, fused LSE epilogue ----------------
// WHICH: 0=proj0 (plain store H0+H0b), 1=head, 2=tail1, 3=tail2 (fused LSE)
// C[m,n] = A[m,:] . W[n,:] (+bias). BM=128, BN=128, BK=32, 8 warps (4m x 2n),
// warp tile 32x64 = 2x8 m16n8k16 fragments.
#define SMS 40   // smem row stride in halves (32 + 8 pad)
template <int WHICH>
__global__ void __launch_bounds__(256) mma_gemm(const float* __restrict__ bias) {
    constexpr bool FUSED = (WHICH != 0);
    constexpr int LD = (WHICH <= 1) ? 1024 : (WHICH == 2 ? 256 : 64);   // K
    constexpr int NTOT = (WHICH == 0) ? 1024 : (WHICH == 1 ? V0 : 40000);
    constexpr int NTILES = (WHICH == 1) ? NT_HEAD : NT_TAIL;

    int M = N_SEQ;
    if (WHICH == 2) M = g_cnt[3];
    if (WHICH == 3) M = g_cnt[4];
    const int bm = blockIdx.y * 128;
    if (bm >= M) return;
    const int bn = blockIdx.x * 128;

    const __nv_bfloat16* A  = (WHICH == 0) ? g_hidden_b : (WHICH == 1) ? g_H0b
                            : (WHICH == 2) ? g_H1b : g_H2b;
    const __nv_bfloat16* Wp = (WHICH == 0) ? g_p0t : (WHICH == 1) ? g_w0b
                            : (WHICH == 2) ? g_w1b : g_w2b;
    float2* part     = (WHICH == 1) ? g_part_head : (WHICH == 2) ? g_part_t1 : g_part_t2;
    const int* labc  = (WHICH == 1) ? g_labc_head : (WHICH == 2) ? g_labc_t1 : g_labc_t2;
    float* labout    = (WHICH == 1) ? g_lab_head : (WHICH == 2) ? g_lab_t1 : g_lab_t2;

    __shared__ __align__(16) uint16_t sA[128][SMS];
    __shared__ __align__(16) uint16_t sB[128][SMS];
    __shared__ float sBias[128];
    __shared__ float2 sPart[2][128];

    const int tid = threadIdx.x;
    const int lane = tid & 31, warp = tid >> 5;
    const int wm = warp & 3, wn = warp >> 2;   // 4 x 2 warp grid
    const uint32_t smA = smem_u32(sA), smB = smem_u32(sB);

    if (FUSED && tid < 128)
        sBias[tid] = (bn + tid < NTOT) ? bias[bn + tid] : 0.f;

    float acc[2][8][4];
#pragma unroll
    for (int mt = 0; mt < 2; mt++)
#pragma unroll
        for (int nt = 0; nt < 8; nt++)
#pragma unroll
            for (int q = 0; q < 4; q++) acc[mt][nt][q] = 0.f;

    for (int k0 = 0; k0 < LD; k0 += 32) {
        __syncthreads();
        // load A/B tiles: 128 rows x 32 halves (64B/row) each; 512 uint4 per tile
#pragma unroll
        for (int p = 0; p < 2; p++) {
            int idx = p * 256 + tid;
            int r = idx >> 2, c = (idx & 3) * 8;
            *(uint4*)&sA[r][c] = *(const uint4*)(A + (size_t)(bm + r) * LD + k0 + c);
            uint4 bvv = make_uint4(0, 0, 0, 0);
            if (bn + r < NTOT) bvv = *(const uint4*)(Wp + (size_t)(bn + r) * LD + k0 + c);
            *(uint4*)&sB[r][c] = bvv;
        }
        __syncthreads();
#pragma unroll
        for (int ks = 0; ks < 2; ks++) {
            const int kk = ks * 16;
            uint32_t af[2][4];
#pragma unroll
            for (int mt = 0; mt < 2; mt++) {
                uint32_t addr = smA +
                    ((uint32_t)((wm * 32 + mt * 16 + (lane & 15)) * SMS + kk + ((lane >> 4) << 3)) << 1);
                ldm_x4(af[mt], addr);
            }
            uint32_t bf[8][2];
#pragma unroll
            for (int nt = 0; nt < 8; nt++) {
                uint32_t addr = smB +
                    ((uint32_t)((wn * 64 + nt * 8 + (lane & 7)) * SMS + kk + (((lane >> 3) & 1) << 3)) << 1);
                ldm_x2(bf[nt], addr);
            }
#pragma unroll
            for (int mt = 0; mt < 2; mt++)
#pragma unroll
                for (int nt = 0; nt < 8; nt++)
                    mma_bf16(acc[mt][nt], af[mt], bf[nt]);
        }
    }
    __syncthreads();

    // ---- epilogue ----
    const int g = lane >> 2, t = lane & 3;
    if (FUSED) {
#pragma unroll
        for (int mt = 0; mt < 2; mt++) {
#pragma unroll
            for (int rs = 0; rs < 2; rs++) {
                const int rloc = wm * 32 + mt * 16 + rs * 8 + g;
                const int m = bm + rloc;
                const bool mok = (m < M);
                const int lc = mok ? labc[m] : -2;
                float vmax = -1e30f;
                float vals[16];
#pragma unroll
                for (int nt = 0; nt < 8; nt++) {
#pragma unroll
                    for (int q = 0; q < 2; q++) {
                        const int ncol = wn * 64 + nt * 8 + 2 * t + q;
                        const int n = bn + ncol;
                        float v = (n < NTOT) ? acc[mt][nt][rs * 2 + q] + sBias[ncol] : -1e30f;
                        vals[nt * 2 + q] = v;
                        if (v > vmax) vmax = v;
                        if (n == lc) labout[m] = v;
                    }
                }
                vmax = fmaxf(vmax, __shfl_xor_sync(0xffffffffu, vmax, 1));
                vmax = fmaxf(vmax, __shfl_xor_sync(0xffffffffu, vmax, 2));
                float s = 0.f;
#pragma unroll
                for (int q = 0; q < 16; q++)
                    if (vals[q] > -1e29f) s += fexp(vals[q] - vmax);
                s += __shfl_xor_sync(0xffffffffu, s, 1);
                s += __shfl_xor_sync(0xffffffffu, s, 2);
                if (t == 0) sPart[wn][rloc] = make_float2(vmax, s);
            }
        }
        __syncthreads();
        if (tid < 128) {
            const int m = bm + tid;
            if (m < M) {
                float2 p0 = sPart[0][tid], p1 = sPart[1][tid];
                float mm = fmaxf(p0.x, p1.x);
                float ss = p0.y * fexp(p0.x - mm) + p1.y * fexp(p1.x - mm);
                part[(size_t)m * NTILES + blockIdx.x] = make_float2(mm, ss);
            }
        }
    } else {
#pragma unroll
        for (int mt = 0; mt < 2; mt++) {
#pragma unroll
            for (int rs = 0; rs < 2; rs++) {
                const int m = bm + wm * 32 + mt * 16 + rs * 8 + g;
#pragma unroll
                for (int nt = 0; nt < 8; nt++) {
#pragma unroll
                    for (int q = 0; q < 2; q++) {
                        const int n = bn + wn * 64 + nt * 8 + 2 * t + q;
                        float v = acc[mt][nt][rs * 2 + q];
                        g_H0[(size_t)m * DPROJ + n] = v;
                        g_H0b[(size_t)m * DPROJ + n] = __float2bfloat16(v);
                    }
                }
            }
        }
    }
}

// ---------------- cluster-token logits + their LSE partial (slot NT_HEAD-1) ----------------
__global__ void __launch_bounds__(128) cluster_cols(const float* __restrict__ cw,
                                                    const float* __restrict__ cb) {
    const int r = blockIdx.x;
    const float* h = g_H0 + (size_t)r * DPROJ;
    float s0 = 0.f, s1 = 0.f;
    for (int k = threadIdx.x; k < DPROJ; k += 128) {
        float hv = h[k];
        s0 = fmaf(hv, cw[k], s0);
        s1 = fmaf(hv, cw[DPROJ + k], s1);
    }
#pragma unroll
    for (int o = 16; o > 0; o >>= 1) {
        s0 += __shfl_down_sync(0xffffffffu, s0, o);
        s1 += __shfl_down_sync(0xffffffffu, s1, o);
    }
    __shared__ float red[2][4];
    const int wid = threadIdx.x >> 5, lane = threadIdx.x & 31;
    if (lane == 0) { red[0][wid] = s0; red[1][wid] = s1; }
    __syncthreads();
    if (threadIdx.x == 0) {
        float c0 = red[0][0] + red[0][1] + red[0][2] + red[0][3] + cb[0];
        float c1 = red[1][0] + red[1][1] + red[1][2] + red[1][3] + cb[1];
        g_clus[r][0] = c0;
        g_clus[r][1] = c1;
        float pm = fmaxf(c0, c1);
        g_part_head[(size_t)r * NT_HEAD + (NT_HEAD - 1)] =
            make_float2(pm, __expf(c0 - pm) + __expf(c1 - pm));
    }
}

// ---------------- combine partials -> per-row LSE (1 warp / row) ----------------
template <int NT, int WHICH>
__global__ void __launch_bounds__(256) reduce_lse() {
    const int r = blockIdx.x * 8 + (threadIdx.x >> 5);
    const int lane = threadIdx.x & 31;
    if (WHICH == 1 && r >= g_cnt[3]) return;
    if (WHICH == 2 && r >= g_cnt[4]) return;
    const float2* part = (WHICH == 0) ? g_part_head : (WHICH == 1) ? g_part_t1 : g_part_t2;
    float m = -1e30f, s = 0.f;
    for (int t = lane; t < NT; t += 32) {
        float2 p = part[(size_t)r * NT + t];
        if (p.x > m) { s = s * __expf(m - p.x) + p.y; m = p.x; }
        else s += p.y * __expf(p.x - m);
    }
#pragma unroll
    for (int o = 16; o > 0; o >>= 1) {
        float m2 = __shfl_xor_sync(0xffffffffu, m, o);
        float s2 = __shfl_xor_sync(0xffffffffu, s, o);
        float mm = fmaxf(m, m2);
        s = s * __expf(m - mm) + s2 * __expf(m2 - mm);
        m = mm;
    }
    if (lane == 0) {
        float v = m + logf(s);
        if (WHICH == 0) g_head_lse[r] = v;
        else if (WHICH == 1) g_t1_lse[r] = v;
        else g_t2_lse[r] = v;
    }
}

// ---------------- finalize ----------------
__global__ void __launch_bounds__(256) finalize_k(const int* __restrict__ labels,
                                                  float* __restrict__ out) {
    const int r = blockIdx.x * 256 + threadIdx.x;
    if (r >= N_SEQ) return;
    const int l = labels[r];
    const float lse = g_head_lse[r];
    float lp;
    if (l < C1) {
        lp = g_lab_head[r] - lse;
    } else if (l < C2) {
        int p = g_pos[0][r];
        lp = (g_clus[r][1] - lse) + (g_lab_t1[p] - g_t1_lse[p]);
    } else {
        int p = g_pos[1][r];
        lp = (g_clus[r][0] - lse) + (g_lab_t2[p] - g_t2_lse[p]);
    }
    out[r] = -lp;
}

// ---------------- launch: kernel launches ONLY ----------------
extern "C" void kernel_launch(void* const* d_in, const int* in_sizes, int n_in,
                              void* d_out, int out_size) {
    const int* x        = (const int*)d_in[0];
    const int* labels   = (const int*)d_in[1];
    const float* emb_w0 = (const float*)d_in[2];
    const float* emb_w1 = (const float*)d_in[3];
    const float* emb_w2 = (const float*)d_in[4];
    const float* emb_p0 = (const float*)d_in[5];
    const float* emb_p1 = (const float*)d_in[6];
    const float* emb_p2 = (const float*)d_in[7];
    const float* out_w0 = (const float*)d_in[8];
    const float* out_b0 = (const float*)d_in[9];
    const float* out_w1 = (const float*)d_in[10];
    const float* out_b1 = (const float*)d_in[11];
    const float* out_w2 = (const float*)d_in[12];
    const float* out_b2 = (const float*)d_in[13];
    const float* out_p0 = (const float*)d_in[14];
    const float* out_p1 = (const float*)d_in[15];
    const float* out_p2 = (const float*)d_in[16];
    const float* clus_w = (const float*)d_in[17];
    const float* clus_b = (const float*)d_in[18];

    // lists + weight conversions
    build_lists<<<1, 256>>>(x, labels);
    cvt_k<0><<<2048, 256>>>(out_w0);
    cvt_k<1><<<2048, 256>>>(out_w1);
    cvt_k<2><<<1024, 256>>>(out_w2);
    transpose_p0<<<dim3(32, 32), dim3(32, 8)>>>(out_p0);

    // adaptive embedding (fp32 SIMT, dual fp32+bf16 scatter)
    dim3 eg(DPROJ / 128, N_SEQ / 128);
    k_emb0<<<eg, 256>>>(emb_w0, emb_p0);
    k_emb1<<<eg, 256>>>(emb_w1, emb_p1);
    k_emb2<<<eg, 256>>>(emb_w2, emb_p2);

    // H0 = hidden @ out_proj0  (mma.sync, plain store)
    mma_gemm<0><<<dim3(8, 16), 256>>>(nullptr);

    // head logits: mma.sync + fused LSE; cluster-token columns
    mma_gemm<1><<<dim3(NT0, 16), 256>>>(out_b0);
    cluster_cols<<<N_SEQ, 128>>>(clus_w, clus_b);

    // tail hidden projections (fp32 SIMT -> bf16)
    k_proj1<<<dim3(2, 16), 256>>>(out_p1);
    k_proj2<<<dim3(1, 16), 256>>>(out_p2);

    // tail logits: mma.sync + fused LSE (compacted rows only)
    mma_gemm<2><<<dim3(NT_TAIL, 16), 256>>>(out_b1);
    mma_gemm<3><<<dim3(NT_TAIL, 16), 256>>>(out_b2);

    // combine partials -> per-row LSE
    reduce_lse<NT_HEAD, 0><<<N_SEQ / 8, 256>>>();
    reduce_lse<NT_TAIL, 1><<<N_SEQ / 8, 256>>>();
    reduce_lse<NT_TAIL, 2><<<N_SEQ / 8, 256>>>();

    // final NLL
    finalize_k<<<N_SEQ / 256, 256>>>(labels, (float*)d_out);
}

// round 7
// speedup vs baseline: 3.0414x; 1.1608x over previous
#include <cuda_runtime.h>
#include <cuda_bf16.h>
#include <math.h>
#include <stdint.h>

#define N_SEQ 2048
#define DPROJ 1024
#define C1 20000
#define C2 60000
#define V0 20000
#define V1 40000
#define V2 40000

#define NT0 157        // ceil(20000/128) head col tiles
#define NT_HEAD 158    // +1 cluster slot
#define NT_TAIL 313    // ceil(40000/128)

// ---------------- static device scratch (allocation-free) ----------------
__device__ float g_hidden[N_SEQ * DPROJ];
__device__ __nv_bfloat16 g_hidden_b[N_SEQ * DPROJ];
__device__ float g_H0[N_SEQ * DPROJ];
__device__ __nv_bfloat16 g_H0b[N_SEQ * DPROJ];
__device__ __nv_bfloat16 g_H1b[N_SEQ * 256];
__device__ __nv_bfloat16 g_H2b[N_SEQ * 64];
__device__ __nv_bfloat16 g_w0b[(size_t)V0 * 1024];
__device__ __nv_bfloat16 g_w1b[(size_t)V1 * 256];
__device__ __nv_bfloat16 g_w2b[(size_t)V2 * 64];
__device__ __nv_bfloat16 g_p0t[(size_t)DPROJ * DPROJ];   // out_proj0 transposed: [n][k]
__device__ float2 g_part_head[(size_t)N_SEQ * NT_HEAD];
__device__ float2 g_part_t1[(size_t)N_SEQ * NT_TAIL];
__device__ float2 g_part_t2[(size_t)N_SEQ * NT_TAIL];
__device__ float g_head_lse[N_SEQ];
__device__ float g_t1_lse[N_SEQ];
__device__ float g_t2_lse[N_SEQ];
__device__ float g_lab_head[N_SEQ];
__device__ float g_lab_t1[N_SEQ];
__device__ float g_lab_t2[N_SEQ];
__device__ float g_clus[N_SEQ][2];
__device__ int g_xl[3][N_SEQ];
__device__ int g_xar[3][N_SEQ];
__device__ int g_ll[2][N_SEQ];
__device__ int g_pos[2][N_SEQ];
__device__ int g_labc_head[N_SEQ];
__device__ int g_labc_t1[N_SEQ];
__device__ int g_labc_t2[N_SEQ];
__device__ int g_cnt[8];

// ---------------- helpers ----------------
static __device__ __forceinline__ uint32_t smem_u32(const void* p) {
    uint32_t a;
    asm("{ .reg .u64 t; cvta.to.shared.u64 t, %1; cvt.u32.u64 %0, t; }" : "=r"(a) : "l"(p));
    return a;
}

// FMA-pipe exp (no MUFU): exp(x)=2^(x*log2e), deg-5 poly
static __device__ __forceinline__ float fexp(float x) {
    float y = fmaxf(x * 1.44269504f, -120.f);
    int e = __float2int_rn(y);
    float f = y - __int2float_rn(e);
    float p = 1.3333558e-3f;
    p = fmaf(p, f, 9.6181291e-3f);
    p = fmaf(p, f, 5.5504109e-2f);
    p = fmaf(p, f, 2.4022650e-1f);
    p = fmaf(p, f, 6.9314718e-1f);
    p = fmaf(p, f, 1.0f);
    return p * __int_as_float((e + 127) << 23);
}

static __device__ __forceinline__ void ldm_x4(uint32_t* r, uint32_t addr) {
    asm volatile("ldmatrix.sync.aligned.m8n8.x4.shared.b16 {%0,%1,%2,%3}, [%4];"
                 : "=r"(r[0]), "=r"(r[1]), "=r"(r[2]), "=r"(r[3]) : "r"(addr));
}
static __device__ __forceinline__ void ldm_x2(uint32_t* r, uint32_t addr) {
    asm volatile("ldmatrix.sync.aligned.m8n8.x2.shared.b16 {%0,%1}, [%2];"
                 : "=r"(r[0]), "=r"(r[1]) : "r"(addr));
}
static __device__ __forceinline__ void mma_bf16(float* c, const uint32_t* a, const uint32_t* b) {
    asm volatile(
        "mma.sync.aligned.m16n8k16.row.col.f32.bf16.bf16.f32 "
        "{%0,%1,%2,%3}, {%4,%5,%6,%7}, {%8,%9}, {%0,%1,%2,%3};"
        : "+f"(c[0]), "+f"(c[1]), "+f"(c[2]), "+f"(c[3])
        : "r"(a[0]), "r"(a[1]), "r"(a[2]), "r"(a[3]), "r"(b[0]), "r"(b[1]));
}
static __device__ __forceinline__ void cpa16(uint32_t dst, const void* src, bool ok) {
    asm volatile("cp.async.cg.shared.global [%0], [%1], 16, %2;"
                 :: "r"(dst), "l"(src), "r"(ok ? 16u : 0u) : "memory");
}
#define CP_COMMIT() asm volatile("cp.async.commit_group;" ::: "memory")
#define CP_WAIT(n)  asm volatile("cp.async.wait_group %0;" :: "n"(n) : "memory")

// ---------------- list building (1 block, deterministic prefix scan) ----------------
__global__ void build_lists(const int* __restrict__ x, const int* __restrict__ labels) {
    __shared__ int base[5][257];
    const int tid = threadIdx.x;
    int lc[5] = {0, 0, 0, 0, 0};
    for (int t = tid * 8; t < tid * 8 + 8; t++) {
        int xv = x[t];
        int c = (xv < C1) ? 0 : ((xv < C2) ? 1 : 2);
        lc[c]++;
        int lv = labels[t];
        if (lv >= C1) lc[3 + (lv >= C2 ? 1 : 0)]++;
    }
    for (int c = 0; c < 5; c++) base[c][tid + 1] = lc[c];
    __syncthreads();
    if (tid < 5) {
        base[tid][0] = 0;
        for (int i = 0; i < 256; i++) base[tid][i + 1] += base[tid][i];
        g_cnt[tid] = base[tid][256];
    }
    __syncthreads();
    int off[5];
    for (int c = 0; c < 5; c++) off[c] = base[c][tid];
    for (int t = tid * 8; t < tid * 8 + 8; t++) {
        int xv = x[t];
        int c = (xv < C1) ? 0 : ((xv < C2) ? 1 : 2);
        int lo = (c == 0) ? 0 : ((c == 1) ? C1 : C2);
        int p = off[c]++;
        g_xl[c][p] = t;
        g_xar[c][p] = xv - lo;
        int lv = labels[t];
        g_labc_head[t] = (lv < C1) ? lv : -1;
        if (lv >= C1) {
            int tc = (lv >= C2) ? 1 : 0;
            int q = off[3 + tc]++;
            g_ll[tc][q] = t;
            g_pos[tc][t] = q;
            if (tc == 0) g_labc_t1[q] = lv - C1;
            else         g_labc_t2[q] = lv - C2;
        }
    }
}

// ---------------- weight conversion fp32 -> bf16 ----------------
template <int W>
__global__ void __launch_bounds__(256) cvt_k(const float* __restrict__ src) {
    __nv_bfloat16* dst = (W == 0) ? g_w0b : (W == 1) ? g_w1b : g_w2b;
    const int n = (W == 0) ? V0 * 1024 : (W == 1) ? V1 * 256 : V2 * 64;
    int i = (blockIdx.x * 256 + threadIdx.x) * 4;
    const int stride = gridDim.x * 256 * 4;
    for (; i < n; i += stride) {
        float4 v = *(const float4*)(src + i);
        *(__nv_bfloat162*)(dst + i)     = __floats2bfloat162_rn(v.x, v.y);
        *(__nv_bfloat162*)(dst + i + 2) = __floats2bfloat162_rn(v.z, v.w);
    }
}

// out_proj0 [K=1024, N=1024] fp32 -> g_p0t [N, K] bf16
__global__ void transpose_p0(const float* __restrict__ src) {
    __shared__ float t[32][33];
    const int k0 = blockIdx.y * 32, n0 = blockIdx.x * 32;
    const int tx = threadIdx.x, ty = threadIdx.y;   // 32 x 8
    for (int r = ty; r < 32; r += 8)
        t[r][tx] = src[(size_t)(k0 + r) * DPROJ + n0 + tx];
    __syncthreads();
    for (int r = ty; r < 32; r += 8)
        g_p0t[(size_t)(n0 + r) * DPROJ + k0 + tx] = __float2bfloat16(t[tx][r]);
}

// ---------------- SIMT fp32 NT GEMM (embeddings; dual fp32+bf16 scatter store) ----------------
__device__ __forceinline__ void gemm_nt_body(
    const float* __restrict__ A, const float* __restrict__ B,
    float* __restrict__ Cf, __nv_bfloat16* __restrict__ Cb,
    int M, int N, int K, long ldC,
    const int* __restrict__ arows, const int* __restrict__ crows,
    float alpha)
{
    const int bm = blockIdx.y * 128, bn = blockIdx.x * 128;
    if (bm >= M) return;
    __shared__ __align__(16) float As[8][132];
    __shared__ __align__(16) float Bs[8][132];
    const int tid = threadIdx.x;
    const int tx = tid & 15, ty = tid >> 4;
    const int lr = tid >> 1;
    const int lk = (tid & 1) * 4;

    const float* aptr = nullptr;
    { int m = bm + lr; if (m < M) { int g = arows ? arows[m] : m; aptr = A + (long)g * K + lk; } }
    const float* bptr = nullptr;
    { int n = bn + lr; if (n < N) bptr = B + (long)n * K + lk; }

    float4 av = aptr ? *(const float4*)aptr : make_float4(0, 0, 0, 0);
    float4 bv = bptr ? *(const float4*)bptr : make_float4(0, 0, 0, 0);

    float acc[8][8] = {};
    for (int k0 = 0; k0 < K; k0 += 8) {
        __syncthreads();
        As[lk + 0][lr] = av.x; As[lk + 1][lr] = av.y; As[lk + 2][lr] = av.z; As[lk + 3][lr] = av.w;
        Bs[lk + 0][lr] = bv.x; Bs[lk + 1][lr] = bv.y; Bs[lk + 2][lr] = bv.z; Bs[lk + 3][lr] = bv.w;
        __syncthreads();
        if (k0 + 8 < K) {
            av = aptr ? *(const float4*)(aptr + k0 + 8) : make_float4(0, 0, 0, 0);
            bv = bptr ? *(const float4*)(bptr + k0 + 8) : make_float4(0, 0, 0, 0);
        }
#pragma unroll
        for (int k = 0; k < 8; k++) {
            float4 a0 = *(const float4*)&As[k][ty * 8];
            float4 a1 = *(const float4*)&As[k][ty * 8 + 4];
            float4 b0 = *(const float4*)&Bs[k][tx * 8];
            float4 b1 = *(const float4*)&Bs[k][tx * 8 + 4];
            float ar[8] = {a0.x, a0.y, a0.z, a0.w, a1.x, a1.y, a1.z, a1.w};
            float br[8] = {b0.x, b0.y, b0.z, b0.w, b1.x, b1.y, b1.z, b1.w};
#pragma unroll
            for (int i = 0; i < 8; i++)
#pragma unroll
                for (int j = 0; j < 8; j++) acc[i][j] = fmaf(ar[i], br[j], acc[i][j]);
        }
    }
#pragma unroll
    for (int i = 0; i < 8; i++) {
        int m = bm + ty * 8 + i;
        if (m >= M) break;
        long cr = crows ? (long)crows[m] : (long)m;
#pragma unroll
        for (int j = 0; j < 8; j++) {
            int n = bn + tx * 8 + j;
            if (n < N) {
                float v = acc[i][j] * alpha;
                Cf[cr * ldC + n] = v;
                Cb[cr * ldC + n] = __float2bfloat16(v);
            }
        }
    }
}

// ---------------- SIMT fp32 NN GEMM (proj1/proj2; bf16 store) ----------------
__device__ __forceinline__ void gemm_nn_body(
    const float* __restrict__ A, const float* __restrict__ B,
    __nv_bfloat16* __restrict__ Cb,
    int M, int N, int K, const int* __restrict__ arows, const int* __restrict__ Mcnt)
{
    if (Mcnt) M = *Mcnt;
    const int bm = blockIdx.y * 128, bn = blockIdx.x * 128;
    if (bm >= M) return;
    __shared__ __align__(16) float As[8][132];
    __shared__ __align__(16) float Bs[8][132];
    const int tid = threadIdx.x;
    const int tx = tid & 15, ty = tid >> 4;
    const int lr = tid >> 1;
    const int lk = (tid & 1) * 4;
    const int bk = tid >> 5;
    const int bnn = (tid & 31) * 4;

    const float* aptr = nullptr;
    { int m = bm + lr; if (m < M) { int g = arows ? arows[m] : m; aptr = A + (long)g * K + lk; } }
    const bool bok = (bn + bnn) < N;
    const float* bbase = B + (long)bk * N + bn + bnn;

    float4 av = aptr ? *(const float4*)aptr : make_float4(0, 0, 0, 0);
    float4 bv = bok ? *(const float4*)bbase : make_float4(0, 0, 0, 0);

    float acc[8][8] = {};
    for (int k0 = 0; k0 < K; k0 += 8) {
        __syncthreads();
        As[lk + 0][lr] = av.x; As[lk + 1][lr] = av.y; As[lk + 2][lr] = av.z; As[lk + 3][lr] = av.w;
        *(float4*)&Bs[bk][bnn] = bv;
        __syncthreads();
        if (k0 + 8 < K) {
            av = aptr ? *(const float4*)(aptr + k0 + 8) : make_float4(0, 0, 0, 0);
            bv = bok ? *(const float4*)(bbase + (long)(k0 + 8) * N) : make_float4(0, 0, 0, 0);
        }
#pragma unroll
        for (int k = 0; k < 8; k++) {
            float4 a0 = *(const float4*)&As[k][ty * 8];
            float4 a1 = *(const float4*)&As[k][ty * 8 + 4];
            float4 b0 = *(const float4*)&Bs[k][tx * 8];
            float4 b1 = *(const float4*)&Bs[k][tx * 8 + 4];
            float ar[8] = {a0.x, a0.y, a0.z, a0.w, a1.x, a1.y, a1.z, a1.w};
            float br[8] = {b0.x, b0.y, b0.z, b0.w, b1.x, b1.y, b1.z, b1.w};
#pragma unroll
            for (int i = 0; i < 8; i++)
#pragma unroll
                for (int j = 0; j < 8; j++) acc[i][j] = fmaf(ar[i], br[j], acc[i][j]);
        }
    }
#pragma unroll
    for (int i = 0; i < 8; i++) {
        int m = bm + ty * 8 + i;
        if (m >= M) break;
#pragma unroll
        for (int j = 0; j < 8; j++) {
            int n = bn + tx * 8 + j;
            if (n < N) Cb[(long)m * N + n] = __float2bfloat16(acc[i][j]);
        }
    }
}

// merged embedding kernel: blockIdx.z selects cluster
__global__ void __launch_bounds__(256) k_emb_all(
    const float* __restrict__ W0, const float* __restrict__ P0,
    const float* __restrict__ W1, const float* __restrict__ P1,
    const float* __restrict__ W2, const float* __restrict__ P2)
{
    const int c = blockIdx.z;
    const float* W = (c == 0) ? W0 : (c == 1) ? W1 : W2;
    const float* P = (c == 0) ? P0 : (c == 1) ? P1 : P2;
    const int K = (c == 0) ? 1024 : (c == 1) ? 256 : 64;
    gemm_nt_body(W, P, g_hidden, g_hidden_b, g_cnt[c], DPROJ, K, DPROJ,
                 g_xar[c], g_xl[c], 32.f);
}
__global__ void __launch_bounds__(256) k_proj1(const float* __restrict__ P) {
    gemm_nn_body(g_hidden, P, g_H1b, N_SEQ, 256, 1024, g_ll[0], &g_cnt[3]);
}
__global__ void __launch_bounds__(256) k_proj2(const float* __restrict__ P) {
    gemm_nn_body(g_hidden, P, g_H2b, N_SEQ, 64, 1024, g_ll[1], &g_cnt[4]);
}

// ---------------- mma.sync bf16 NT GEMM, cp.async 2-stage pipeline, fused LSE ----------------
// WHICH: 0=proj0 (plain store H0+H0b), 1=head, 2=tail1, 3=tail2 (fused LSE)
// C[m,n] = A[m,:] . W[n,:] (+bias). BM=128, BN=128, BK=32, 8 warps (4m x 2n),
// warp tile 32x64 = 2x8 m16n8k16 fragments.
#define SMS 40   // smem row stride in halves (32 + 8 pad; 80B rows keep 16B alignment)
template <int WHICH>
__global__ void __launch_bounds__(256) mma_gemm(const float* __restrict__ bias) {
    constexpr bool FUSED = (WHICH != 0);
    constexpr int LD = (WHICH <= 1) ? 1024 : (WHICH == 2 ? 256 : 64);   // K
    constexpr int KCH = LD / 32;
    constexpr int NTOT = (WHICH == 0) ? 1024 : (WHICH == 1 ? V0 : 40000);
    constexpr int NTILES = (WHICH == 1) ? NT_HEAD : NT_TAIL;

    int M = N_SEQ;
    if (WHICH == 2) M = g_cnt[3];
    if (WHICH == 3) M = g_cnt[4];
    const int bm = blockIdx.y * 128;
    if (bm >= M) return;
    const int bn = blockIdx.x * 128;

    const __nv_bfloat16* A  = (WHICH == 0) ? g_hidden_b : (WHICH == 1) ? g_H0b
                            : (WHICH == 2) ? g_H1b : g_H2b;
    const __nv_bfloat16* Wp = (WHICH == 0) ? g_p0t : (WHICH == 1) ? g_w0b
                            : (WHICH == 2) ? g_w1b : g_w2b;
    float2* part     = (WHICH == 1) ? g_part_head : (WHICH == 2) ? g_part_t1 : g_part_t2;
    const int* labc  = (WHICH == 1) ? g_labc_head : (WHICH == 2) ? g_labc_t1 : g_labc_t2;
    float* labout    = (WHICH == 1) ? g_lab_head : (WHICH == 2) ? g_lab_t1 : g_lab_t2;

    __shared__ __align__(16) uint16_t sA[2][128][SMS];
    __shared__ __align__(16) uint16_t sB[2][128][SMS];
    __shared__ float sBias[128];
    __shared__ float2 sPart[2][128];

    const int tid = threadIdx.x;
    const int lane = tid & 31, warp = tid >> 5;
    const int wm = warp & 3, wn = warp >> 2;   // 4 x 2 warp grid
    const uint32_t smA = smem_u32(sA), smB = smem_u32(sB);
    constexpr uint32_t STAGE = 128 * SMS * 2;  // bytes per stage

    if (FUSED && tid < 128)
        sBias[tid] = (bn + tid < NTOT) ? bias[bn + tid] : 0.f;

    // per-thread load slots: 4 rows of A + 4 rows of B per stage (128 rows / 32 row-groups)
    const int lrow = tid >> 2;           // 0..63
    const int lcol = (tid & 3) * 8;      // 0,8,16,24 halves
    const uint32_t sAoff = (uint32_t)(lrow * SMS + lcol) << 1;
    const uint32_t sBoff = sAoff;

    float acc[2][8][4];
#pragma unroll
    for (int mt = 0; mt < 2; mt++)
#pragma unroll
        for (int nt = 0; nt < 8; nt++)
#pragma unroll
            for (int q = 0; q < 4; q++) acc[mt][nt][q] = 0.f;

    // ---- prologue: stage 0 ----
    {
        const int k0 = 0;
#pragma unroll
        for (int p = 0; p < 2; p++) {
            int r = p * 64 + lrow;
            cpa16(smA + sAoff + (uint32_t)(p * 64 * SMS * 2),
                  A + (size_t)(bm + r) * LD + k0 + lcol, true);
            cpa16(smB + sBoff + (uint32_t)(p * 64 * SMS * 2),
                  Wp + (size_t)(bn + r) * LD + k0 + lcol, bn + r < NTOT);
        }
        CP_COMMIT();
    }

    for (int ch = 0; ch < KCH; ch++) {
        const int st = ch & 1;
        if (ch + 1 < KCH) {
            const int k0 = (ch + 1) * 32;
            const uint32_t sb = (uint32_t)((ch + 1) & 1) * STAGE;
#pragma unroll
            for (int p = 0; p < 2; p++) {
                int r = p * 64 + lrow;
                cpa16(smA + sb + sAoff + (uint32_t)(p * 64 * SMS * 2),
                      A + (size_t)(bm + r) * LD + k0 + lcol, true);
                cpa16(smB + sb + sBoff + (uint32_t)(p * 64 * SMS * 2),
                      Wp + (size_t)(bn + r) * LD + k0 + lcol, bn + r < NTOT);
            }
            CP_COMMIT();
            CP_WAIT(1);
        } else {
            CP_WAIT(0);
        }
        __syncthreads();

        const uint32_t base = (uint32_t)st * STAGE;
#pragma unroll
        for (int ks = 0; ks < 2; ks++) {
            const int kk = ks * 16;
            uint32_t af[2][4];
#pragma unroll
            for (int mt = 0; mt < 2; mt++) {
                uint32_t addr = smA + base +
                    ((uint32_t)((wm * 32 + mt * 16 + (lane & 15)) * SMS + kk + ((lane >> 4) << 3)) << 1);
                ldm_x4(af[mt], addr);
            }
            uint32_t bf[8][2];
#pragma unroll
            for (int nt = 0; nt < 8; nt++) {
                uint32_t addr = smB + base +
                    ((uint32_t)((wn * 64 + nt * 8 + (lane & 7)) * SMS + kk + (((lane >> 3) & 1) << 3)) << 1);
                ldm_x2(bf[nt], addr);
            }
#pragma unroll
            for (int mt = 0; mt < 2; mt++)
#pragma unroll
                for (int nt = 0; nt < 8; nt++)
                    mma_bf16(acc[mt][nt], af[mt], bf[nt]);
        }
        __syncthreads();
    }

    // ---- epilogue ----
    const int g = lane >> 2, t = lane & 3;
    if (FUSED) {
#pragma unroll
        for (int mt = 0; mt < 2; mt++) {
#pragma unroll
            for (int rs = 0; rs < 2; rs++) {
                const int rloc = wm * 32 + mt * 16 + rs * 8 + g;
                const int m = bm + rloc;
                const bool mok = (m < M);
                const int lc = mok ? labc[m] : -2;
                float vmax = -1e30f;
                float vals[16];
#pragma unroll
                for (int nt = 0; nt < 8; nt++) {
#pragma unroll
                    for (int q = 0; q < 2; q++) {
                        const int ncol = wn * 64 + nt * 8 + 2 * t + q;
                        const int n = bn + ncol;
                        float v = (n < NTOT) ? acc[mt][nt][rs * 2 + q] + sBias[ncol] : -1e30f;
                        vals[nt * 2 + q] = v;
                        if (v > vmax) vmax = v;
                        if (n == lc) labout[m] = v;
                    }
                }
                vmax = fmaxf(vmax, __shfl_xor_sync(0xffffffffu, vmax, 1));
                vmax = fmaxf(vmax, __shfl_xor_sync(0xffffffffu, vmax, 2));
                float s = 0.f;
#pragma unroll
                for (int q = 0; q < 16; q++)
                    if (vals[q] > -1e29f) s += fexp(vals[q] - vmax);
                s += __shfl_xor_sync(0xffffffffu, s, 1);
                s += __shfl_xor_sync(0xffffffffu, s, 2);
                if (t == 0) sPart[wn][rloc] = make_float2(vmax, s);
            }
        }
        __syncthreads();
        if (tid < 128) {
            const int m = bm + tid;
            if (m < M) {
                float2 p0 = sPart[0][tid], p1 = sPart[1][tid];
                float mm = fmaxf(p0.x, p1.x);
                float ss = p0.y * fexp(p0.x - mm) + p1.y * fexp(p1.x - mm);
                part[(size_t)m * NTILES + blockIdx.x] = make_float2(mm, ss);
            }
        }
    } else {
#pragma unroll
        for (int mt = 0; mt < 2; mt++) {
#pragma unroll
            for (int rs = 0; rs < 2; rs++) {
                const int m = bm + wm * 32 + mt * 16 + rs * 8 + g;
#pragma unroll
                for (int nt = 0; nt < 8; nt++) {
#pragma unroll
                    for (int q = 0; q < 2; q++) {
                        const int n = bn + wn * 64 + nt * 8 + 2 * t + q;
                        float v = acc[mt][nt][rs * 2 + q];
                        g_H0[(size_t)m * DPROJ + n] = v;
                        g_H0b[(size_t)m * DPROJ + n] = __float2bfloat16(v);
                    }
                }
            }
        }
    }
}

// ---------------- cluster-token logits + their LSE partial (slot NT_HEAD-1) ----------------
__global__ void __launch_bounds__(128) cluster_cols(const float* __restrict__ cw,
                                                    const float* __restrict__ cb) {
    const int r = blockIdx.x;
    const float* h = g_H0 + (size_t)r * DPROJ;
    float s0 = 0.f, s1 = 0.f;
    for (int k = threadIdx.x; k < DPROJ; k += 128) {
        float hv = h[k];
        s0 = fmaf(hv, cw[k], s0);
        s1 = fmaf(hv, cw[DPROJ + k], s1);
    }
#pragma unroll
    for (int o = 16; o > 0; o >>= 1) {
        s0 += __shfl_down_sync(0xffffffffu, s0, o);
        s1 += __shfl_down_sync(0xffffffffu, s1, o);
    }
    __shared__ float red[2][4];
    const int wid = threadIdx.x >> 5, lane = threadIdx.x & 31;
    if (lane == 0) { red[0][wid] = s0; red[1][wid] = s1; }
    __syncthreads();
    if (threadIdx.x == 0) {
        float c0 = red[0][0] + red[0][1] + red[0][2] + red[0][3] + cb[0];
        float c1 = red[1][0] + red[1][1] + red[1][2] + red[1][3] + cb[1];
        g_clus[r][0] = c0;
        g_clus[r][1] = c1;
        float pm = fmaxf(c0, c1);
        g_part_head[(size_t)r * NT_HEAD + (NT_HEAD - 1)] =
            make_float2(pm, __expf(c0 - pm) + __expf(c1 - pm));
    }
}

// ---------------- combine partials -> per-row LSE (1 warp / row) ----------------
template <int NT, int WHICH>
__global__ void __launch_bounds__(256) reduce_lse() {
    const int r = blockIdx.x * 8 + (threadIdx.x >> 5);
    const int lane = threadIdx.x & 31;
    if (WHICH == 1 && r >= g_cnt[3]) return;
    if (WHICH == 2 && r >= g_cnt[4]) return;
    const float2* part = (WHICH == 0) ? g_part_head : (WHICH == 1) ? g_part_t1 : g_part_t2;
    float m = -1e30f, s = 0.f;
    for (int t = lane; t < NT; t += 32) {
        float2 p = part[(size_t)r * NT + t];
        if (p.x > m) { s = s * __expf(m - p.x) + p.y; m = p.x; }
        else s += p.y * __expf(p.x - m);
    }
#pragma unroll
    for (int o = 16; o > 0; o >>= 1) {
        float m2 = __shfl_xor_sync(0xffffffffu, m, o);
        float s2 = __shfl_xor_sync(0xffffffffu, s, o);
        float mm = fmaxf(m, m2);
        s = s * __expf(m - mm) + s2 * __expf(m2 - mm);
        m = mm;
    }
    if (lane == 0) {
        float v = m + logf(s);
        if (WHICH == 0) g_head_lse[r] = v;
        else if (WHICH == 1) g_t1_lse[r] = v;
        else g_t2_lse[r] = v;
    }
}

// ---------------- finalize ----------------
__global__ void __launch_bounds__(256) finalize_k(const int* __restrict__ labels,
                                                  float* __restrict__ out) {
    const int r = blockIdx.x * 256 + threadIdx.x;
    if (r >= N_SEQ) return;
    const int l = labels[r];
    const float lse = g_head_lse[r];
    float lp;
    if (l < C1) {
        lp = g_lab_head[r] - lse;
    } else if (l < C2) {
        int p = g_pos[0][r];
        lp = (g_clus[r][1] - lse) + (g_lab_t1[p] - g_t1_lse[p]);
    } else {
        int p = g_pos[1][r];
        lp = (g_clus[r][0] - lse) + (g_lab_t2[p] - g_t2_lse[p]);
    }
    out[r] = -lp;
}

// ---------------- launch: kernel launches ONLY ----------------
extern "C" void kernel_launch(void* const* d_in, const int* in_sizes, int n_in,
                              void* d_out, int out_size) {
    const int* x        = (const int*)d_in[0];
    const int* labels   = (const int*)d_in[1];
    const float* emb_w0 = (const float*)d_in[2];
    const float* emb_w1 = (const float*)d_in[3];
    const float* emb_w2 = (const float*)d_in[4];
    const float* emb_p0 = (const float*)d_in[5];
    const float* emb_p1 = (const float*)d_in[6];
    const float* emb_p2 = (const float*)d_in[7];
    const float* out_w0 = (const float*)d_in[8];
    const float* out_b0 = (const float*)d_in[9];
    const float* out_w1 = (const float*)d_in[10];
    const float* out_b1 = (const float*)d_in[11];
    const float* out_w2 = (const float*)d_in[12];
    const float* out_b2 = (const float*)d_in[13];
    const float* out_p0 = (const float*)d_in[14];
    const float* out_p1 = (const float*)d_in[15];
    const float* out_p2 = (const float*)d_in[16];
    const float* clus_w = (const float*)d_in[17];
    const float* clus_b = (const float*)d_in[18];

    // lists + weight conversions
    build_lists<<<1, 256>>>(x, labels);
    cvt_k<0><<<2048, 256>>>(out_w0);
    cvt_k<1><<<2048, 256>>>(out_w1);
    cvt_k<2><<<1024, 256>>>(out_w2);
    transpose_p0<<<dim3(32, 32), dim3(32, 8)>>>(out_p0);

    // adaptive embedding (merged: one launch, z = cluster)
    k_emb_all<<<dim3(8, 16, 3), 256>>>(emb_w0, emb_p0, emb_w1, emb_p1, emb_w2, emb_p2);

    // H0 = hidden @ out_proj0  (mma.sync pipelined, plain store)
    mma_gemm<0><<<dim3(8, 16), 256>>>(nullptr);

    // head logits: mma.sync pipelined + fused LSE; cluster-token columns
    mma_gemm<1><<<dim3(NT0, 16), 256>>>(out_b0);
    cluster_cols<<<N_SEQ, 128>>>(clus_w, clus_b);

    // tail hidden projections (fp32 SIMT -> bf16)
    k_proj1<<<dim3(2, 16), 256>>>(out_p1);
    k_proj2<<<dim3(1, 16), 256>>>(out_p2);

    // tail logits: mma.sync pipelined + fused LSE (compacted rows only)
    mma_gemm<2><<<dim3(NT_TAIL, 16), 256>>>(out_b1);
    mma_gemm<3><<<dim3(NT_TAIL, 16), 256>>>(out_b2);

    // combine partials -> per-row LSE
    reduce_lse<NT_HEAD, 0><<<N_SEQ / 8, 256>>>();
    reduce_lse<NT_TAIL, 1><<<N_SEQ / 8, 256>>>();
    reduce_lse<NT_TAIL, 2><<<N_SEQ / 8, 256>>>();

    // final NLL
    finalize_k<<<N_SEQ / 256, 256>>>(labels, (float*)d_out);
}